// round 11
// baseline (speedup 1.0000x reference)
#include <cuda_runtime.h>
#include <cuda_bf16.h>
#include <cstdint>

// PCEN, 10 smoother coefficients.
//   m[s,t] = (1-s)*m[s,t-1] + s*x[t],  m[s,0] = x[0]
//   out = (x*(EPS+m)^(-alpha) + delta)^r - delta^r
//
// R11: software-pipelined chunks. Loop body: load(ch+1) + scan(ch+1), then
// epilogue(ch). Scan keeps only the carry/Mprev (epilogue re-runs the IIR
// seeded with Mprev — the reference recurrence itself), so pipeline state is
// tiny (no l[] spills, R10's failure). The 7-deep SHFL chain of scan(ch+1)
// interleaves with ~300 independent epilogue instructions of chunk ch.
// RPT=8, CPW=2, 3 MUFU + 1 poly-ex2 per element.

#define PCEN_EPS 1e-5f
#define NS 10
#define CPW 2
#define NPAIR (NS / CPW)
#define TT 2048
#define RPT 8
#define CHUNK (32 * RPT)          // 256
#define NCHUNK (TT / CHUNK)       // 8

__device__ __forceinline__ float fast_ex2(float v) {
    float r; asm("ex2.approx.ftz.f32 %0, %1;" : "=f"(r) : "f"(v)); return r;
}
__device__ __forceinline__ float fast_lg2(float v) {
    float r; asm("lg2.approx.ftz.f32 %0, %1;" : "=f"(r) : "f"(v)); return r;
}

// 2^v on FMA/ALU pipes (no MUFU). Valid for |v| < ~126.
__device__ __forceinline__ float poly_ex2(float v) {
    const float magic = 12582912.0f;           // 1.5 * 2^23
    float fl = v + magic;
    int   iv = __float_as_int(fl);
    float t  = v - (fl - magic);               // t in [-0.5, 0.5]
    float u  = t * 0.6931471805599453f;
    float p  = fmaf(u, 8.3333333e-3f, 4.1666667e-2f);
    p = fmaf(p, u, 0.16666667f);
    p = fmaf(p, u, 0.5f);
    p = fmaf(p, u, 1.0f);
    p = fmaf(p, u, 1.0f);
    return __int_as_float(__float_as_int(p) + (iv << 23));
}

__device__ __forceinline__ float pcen_elem(float xv, float m,
                                           float alpha, float delta,
                                           float r, float delta_r) {
    const float sm = fast_ex2(-alpha * fast_lg2(PCEN_EPS + m));
    return poly_ex2(r * fast_lg2(fmaf(xv, sm, delta))) - delta_r;
}

__global__ __launch_bounds__(128) void pcen_kernel(
    const float* __restrict__ x,
    const float* __restrict__ s_log,
    const float* __restrict__ alpha_log,
    const float* __restrict__ delta_log,
    const float* __restrict__ r_log,
    float* __restrict__ out,
    int F, int BF)
{
    const int gwarp = (blockIdx.x * blockDim.x + threadIdx.x) >> 5;
    const int lane  = threadIdx.x & 31;
    if (gwarp >= BF * NPAIR) return;

    const int row  = gwarp / NPAIR;
    const int pair = gwarp % NPAIR;
    const int i0   = pair * CPW;

    const int b = row / F;
    const int f = row % F;

    const float alpha = __expf(alpha_log[f]);
    const float delta = __expf(delta_log[f]);
    const float r     = __expf(r_log[f]);
    const float delta_r = fast_ex2(r * fast_lg2(delta));

    const float4* __restrict__ xp4 = (const float4*)(x + (size_t)row * TT);
    float* __restrict__ op = out + (((size_t)b * NS + i0) * F + f) * (size_t)TT;
    const size_t s_stride = (size_t)F * TT;

    // persistent per-chain state: 5 regs per chain
    float sv[CPW], a1[CPW], a8[CPW], a8lane[CPW], carry[CPW];

    const float x0 = ((const float*)xp4)[0];

    #pragma unroll
    for (int c = 0; c < CPW; c++) {
        const float s = __expf(s_log[i0 + c]);
        sv[c] = s;
        const float a = 1.0f - s;
        a1[c] = a;
        const float a2 = a * a;
        const float a4 = a2 * a2;
        a8[c] = a4 * a4;
        const float a16  = a8[c] * a8[c];
        const float a32  = a16 * a16;
        const float a64  = a32 * a32;
        const float a128 = a64 * a64;
        float ap = 1.0f;                        // (a^8)^lane
        if (lane & 1)  ap *= a8[c];
        if (lane & 2)  ap *= a16;
        if (lane & 4)  ap *= a32;
        if (lane & 8)  ap *= a64;
        if (lane & 16) ap *= a128;
        a8lane[c] = ap;
        carry[c] = x0;   // m_{-1} = x0 -> m_0 = x0 (reference init)
    }

    // ---- scan phase helper (macro-like lambda): produces Mprev, updates carry
    auto scan_phase = [&](const float4& xa, const float4& xb, float* M) {
        #pragma unroll
        for (int c = 0; c < CPW; c++) {
            const float s = sv[c];
            const float a = a1[c];
            // lane aggregate l7 (intermediates discarded)
            float l = s * xa.x;
            l = fmaf(a, l, s * xa.y);
            l = fmaf(a, l, s * xa.z);
            l = fmaf(a, l, s * xa.w);
            l = fmaf(a, l, s * xb.x);
            l = fmaf(a, l, s * xb.y);
            l = fmaf(a, l, s * xb.z);
            l = fmaf(a, l, s * xb.w);

            const float a16  = a8[c] * a8[c];
            const float a32  = a16 * a16;
            const float a64  = a32 * a32;
            const float a128 = a64 * a64;

            float S = l;
            float v;
            v = __shfl_up_sync(0xFFFFFFFFu, S, 1);  if (lane >= 1)  S = fmaf(a8[c], v, S);
            v = __shfl_up_sync(0xFFFFFFFFu, S, 2);  if (lane >= 2)  S = fmaf(a16,   v, S);
            v = __shfl_up_sync(0xFFFFFFFFu, S, 4);  if (lane >= 4)  S = fmaf(a32,   v, S);
            v = __shfl_up_sync(0xFFFFFFFFu, S, 8);  if (lane >= 8)  S = fmaf(a64,   v, S);
            v = __shfl_up_sync(0xFFFFFFFFu, S, 16); if (lane >= 16) S = fmaf(a128,  v, S);

            const float P = __shfl_up_sync(0xFFFFFFFFu, S, 1);
            M[c] = (lane == 0) ? carry[c] : fmaf(a8lane[c], carry[c], P);
            const float S31 = __shfl_sync(0xFFFFFFFFu, S, 31);
            carry[c] = fmaf(a128 * a128, carry[c], S31);
        }
    };

    // ---- epilogue phase: reference recurrence seeded with Mprev ----
    auto epi_phase = [&](const float4& xa, const float4& xb,
                         const float* M, int ch) {
        #pragma unroll
        for (int c = 0; c < CPW; c++) {
            const float s = sv[c];
            const float a = a1[c];
            float* o = op + (size_t)c * s_stride + (size_t)ch * CHUNK + lane * RPT;
            float m = M[c];
            float4 oa, ob;
            m = fmaf(a, m, s * xa.x); oa.x = pcen_elem(xa.x, m, alpha, delta, r, delta_r);
            m = fmaf(a, m, s * xa.y); oa.y = pcen_elem(xa.y, m, alpha, delta, r, delta_r);
            m = fmaf(a, m, s * xa.z); oa.z = pcen_elem(xa.z, m, alpha, delta, r, delta_r);
            m = fmaf(a, m, s * xa.w); oa.w = pcen_elem(xa.w, m, alpha, delta, r, delta_r);
            m = fmaf(a, m, s * xb.x); ob.x = pcen_elem(xb.x, m, alpha, delta, r, delta_r);
            m = fmaf(a, m, s * xb.y); ob.y = pcen_elem(xb.y, m, alpha, delta, r, delta_r);
            m = fmaf(a, m, s * xb.z); ob.z = pcen_elem(xb.z, m, alpha, delta, r, delta_r);
            m = fmaf(a, m, s * xb.w); ob.w = pcen_elem(xb.w, m, alpha, delta, r, delta_r);
            *(float4*)o       = oa;
            *(float4*)(o + 4) = ob;
        }
    };

    // ---- software pipeline: scan(ch+1) overlaps epilogue(ch) ----
    float4 xa0 = xp4[lane * 2];
    float4 xb0 = xp4[lane * 2 + 1];
    float M0[CPW], M1[CPW];
    scan_phase(xa0, xb0, M0);

    #pragma unroll 1
    for (int ch = 0; ch < NCHUNK - 1; ch++) {
        const int base4 = (ch + 1) * 64 + lane * 2;
        const float4 xa1 = xp4[base4];
        const float4 xb1 = xp4[base4 + 1];
        scan_phase(xa1, xb1, M1);          // depends only on carry from scan(ch)
        epi_phase(xa0, xb0, M0, ch);       // independent -> interleaves with scan
        xa0 = xa1; xb0 = xb1;
        M0[0] = M1[0];
        #if CPW > 1
        M0[1] = M1[1];
        #endif
    }
    epi_phase(xa0, xb0, M0, NCHUNK - 1);
}

extern "C" void kernel_launch(void* const* d_in, const int* in_sizes, int n_in,
                              void* d_out, int out_size)
{
    const float* x         = (const float*)d_in[0];
    const float* s_log     = (const float*)d_in[1];
    const float* alpha_log = (const float*)d_in[2];
    const float* delta_log = (const float*)d_in[3];
    const float* r_log     = (const float*)d_in[4];
    float* out = (float*)d_out;

    const int F  = in_sizes[2];
    const int BF = in_sizes[0] / TT;

    const int total_warps = BF * NPAIR;
    const int threads = 128;
    const int warps_per_block = threads / 32;
    const int blocks = (total_warps + warps_per_block - 1) / warps_per_block;

    pcen_kernel<<<blocks, threads>>>(x, s_log, alpha_log, delta_log, r_log,
                                     out, F, BF);
}

// round 12
// speedup vs baseline: 1.2947x; 1.2947x over previous
#include <cuda_runtime.h>
#include <cuda_bf16.h>
#include <cstdint>

// PCEN, 10 smoother coefficients.
//   m[s,t] = (1-s)*m[s,t-1] + s*x[t],  m[s,0] = x[0]
//   out = (x*(EPS+m)^(-alpha) + delta)^r - delta^r
//
// R12: R8 structure (RPT=8, CPW=2, fold-based epilogue) with two FMA-pipe
// cuts: (1) unnormalized IIR g = x + a*g (m = s*g), removing the s*x mul and
// turning EPS+m into fma(s,gm,EPS); (2) poly_ex2 degree 4. fma-pipe work
// 13 -> 11 ops/elem, balancing against the 3-MUFU XU floor.

#define PCEN_EPS 1e-5f
#define NS 10
#define CPW 2
#define NPAIR (NS / CPW)
#define TT 2048
#define RPT 8
#define CHUNK (32 * RPT)          // 256
#define NCHUNK (TT / CHUNK)       // 8

__device__ __forceinline__ float fast_ex2(float v) {
    float r; asm("ex2.approx.ftz.f32 %0, %1;" : "=f"(r) : "f"(v)); return r;
}
__device__ __forceinline__ float fast_lg2(float v) {
    float r; asm("lg2.approx.ftz.f32 %0, %1;" : "=f"(r) : "f"(v)); return r;
}

// 2^v on FMA/ALU pipes (no MUFU), degree-4 (rel err ~4e-5). |v| < ~126.
__device__ __forceinline__ float poly_ex2(float v) {
    const float magic = 12582912.0f;           // 1.5 * 2^23
    float fl = v + magic;
    int   iv = __float_as_int(fl);
    float t  = v - (fl - magic);               // t in [-0.5, 0.5]
    float u  = t * 0.6931471805599453f;
    float p  = fmaf(u, 4.1666667e-2f, 0.16666667f);
    p = fmaf(p, u, 0.5f);
    p = fmaf(p, u, 1.0f);
    p = fmaf(p, u, 1.0f);
    return __int_as_float(__float_as_int(p) + (iv << 23));
}

// epilogue: em = EPS+m already formed by caller
__device__ __forceinline__ float pcen_elem(float xv, float em,
                                           float alpha, float delta,
                                           float r, float delta_r) {
    const float sm = fast_ex2(-alpha * fast_lg2(em));
    return poly_ex2(r * fast_lg2(fmaf(xv, sm, delta))) - delta_r;
}

__global__ __launch_bounds__(128) void pcen_kernel(
    const float* __restrict__ x,
    const float* __restrict__ s_log,
    const float* __restrict__ alpha_log,
    const float* __restrict__ delta_log,
    const float* __restrict__ r_log,
    float* __restrict__ out,
    int F, int BF)
{
    const int gwarp = (blockIdx.x * blockDim.x + threadIdx.x) >> 5;
    const int lane  = threadIdx.x & 31;
    if (gwarp >= BF * NPAIR) return;

    const int row  = gwarp / NPAIR;
    const int pair = gwarp % NPAIR;
    const int i0   = pair * CPW;

    const int b = row / F;
    const int f = row % F;

    const float alpha = __expf(alpha_log[f]);
    const float delta = __expf(delta_log[f]);
    const float r     = __expf(r_log[f]);
    const float delta_r = fast_ex2(r * fast_lg2(delta));

    const float4* __restrict__ xp4 = (const float4*)(x + (size_t)row * TT);
    float* __restrict__ op = out + (((size_t)b * NS + i0) * F + f) * (size_t)TT;
    const size_t s_stride = (size_t)F * TT;

    // persistent per-chain state: 11 regs per chain
    float sv[CPW], a1[CPW], a2[CPW], a4[CPW], a8[CPW];
    float a16[CPW], a32[CPW], a64[CPW], a128[CPW];
    float a8lane[CPW], carry[CPW];   // carry in g-units (m = s*g)

    const float x0 = ((const float*)xp4)[0];

    #pragma unroll
    for (int c = 0; c < CPW; c++) {
        const float s = __expf(s_log[i0 + c]);
        sv[c] = s;
        const float a = 1.0f - s;
        a1[c]   = a;
        a2[c]   = a * a;
        a4[c]   = a2[c] * a2[c];
        a8[c]   = a4[c] * a4[c];
        a16[c]  = a8[c] * a8[c];
        a32[c]  = a16[c] * a16[c];
        a64[c]  = a32[c] * a32[c];
        a128[c] = a64[c] * a64[c];
        float ap = 1.0f;                        // (a^8)^lane
        if (lane & 1)  ap *= a8[c];
        if (lane & 2)  ap *= a16[c];
        if (lane & 4)  ap *= a32[c];
        if (lane & 8)  ap *= a64[c];
        if (lane & 16) ap *= a128[c];
        a8lane[c] = ap;
        // g_{-1} = x0/s  ->  m_{-1} = x0  ->  m_0 = x0 (reference init)
        carry[c] = __fdividef(x0, s);
    }

    for (int ch = 0; ch < NCHUNK; ch++) {
        // lane owns t in [ch*256 + lane*8, +8): two float4 loads
        const int base4 = ch * 64 + lane * 2;
        const float4 xa = xp4[base4];
        const float4 xb = xp4[base4 + 1];

        #pragma unroll
        for (int c = 0; c < CPW; c++) {
            const float s = sv[c];
            const float a = a1[c];
            // unnormalized local IIR g_j = x_j + a*g_{j-1} (zero init): 7 fma
            const float g0 = xa.x;
            const float g1 = fmaf(a, g0, xa.y);
            const float g2 = fmaf(a, g1, xa.z);
            const float g3 = fmaf(a, g2, xa.w);
            const float g4 = fmaf(a, g3, xb.x);
            const float g5 = fmaf(a, g4, xb.y);
            const float g6 = fmaf(a, g5, xb.z);
            const float g7 = fmaf(a, g6, xb.w);

            // Kogge-Stone over lane aggregates (ratio a^8), g-units
            float S = g7;
            float v;
            v = __shfl_up_sync(0xFFFFFFFFu, S, 1);  if (lane >= 1)  S = fmaf(a8[c],   v, S);
            v = __shfl_up_sync(0xFFFFFFFFu, S, 2);  if (lane >= 2)  S = fmaf(a16[c],  v, S);
            v = __shfl_up_sync(0xFFFFFFFFu, S, 4);  if (lane >= 4)  S = fmaf(a32[c],  v, S);
            v = __shfl_up_sync(0xFFFFFFFFu, S, 8);  if (lane >= 8)  S = fmaf(a64[c],  v, S);
            v = __shfl_up_sync(0xFFFFFFFFu, S, 16); if (lane >= 16) S = fmaf(a128[c], v, S);

            const float P = __shfl_up_sync(0xFFFFFFFFu, S, 1);
            const float Mg = (lane == 0) ? carry[c]
                                         : fmaf(a8lane[c], carry[c], P);
            const float S31 = __shfl_sync(0xFFFFFFFFu, S, 31);
            carry[c] = fmaf(a128[c] * a128[c], carry[c], S31);

            // fold + epilogue: em_j = fma(s, g_j + a^{j+1}*Mg, EPS)
            const float a3 = a1[c] * a2[c];
            const float a5 = a1[c] * a4[c];
            const float a6 = a2[c] * a4[c];
            const float a7 = a3 * a4[c];

            float* o = op + (size_t)c * s_stride + (size_t)ch * CHUNK + lane * RPT;

            {
                const float em0 = fmaf(s, fmaf(a1[c], Mg, g0), PCEN_EPS);
                const float em1 = fmaf(s, fmaf(a2[c], Mg, g1), PCEN_EPS);
                const float em2 = fmaf(s, fmaf(a3,    Mg, g2), PCEN_EPS);
                const float em3 = fmaf(s, fmaf(a4[c], Mg, g3), PCEN_EPS);
                float4 oa;
                oa.x = pcen_elem(xa.x, em0, alpha, delta, r, delta_r);
                oa.y = pcen_elem(xa.y, em1, alpha, delta, r, delta_r);
                oa.z = pcen_elem(xa.z, em2, alpha, delta, r, delta_r);
                oa.w = pcen_elem(xa.w, em3, alpha, delta, r, delta_r);
                *(float4*)o = oa;
            }
            {
                const float em4 = fmaf(s, fmaf(a5,    Mg, g4), PCEN_EPS);
                const float em5 = fmaf(s, fmaf(a6,    Mg, g5), PCEN_EPS);
                const float em6 = fmaf(s, fmaf(a7,    Mg, g6), PCEN_EPS);
                const float em7 = fmaf(s, fmaf(a8[c], Mg, g7), PCEN_EPS);
                float4 ob;
                ob.x = pcen_elem(xb.x, em4, alpha, delta, r, delta_r);
                ob.y = pcen_elem(xb.y, em5, alpha, delta, r, delta_r);
                ob.z = pcen_elem(xb.z, em6, alpha, delta, r, delta_r);
                ob.w = pcen_elem(xb.w, em7, alpha, delta, r, delta_r);
                *(float4*)(o + 4) = ob;
            }
        }
    }
}

extern "C" void kernel_launch(void* const* d_in, const int* in_sizes, int n_in,
                              void* d_out, int out_size)
{
    const float* x         = (const float*)d_in[0];
    const float* s_log     = (const float*)d_in[1];
    const float* alpha_log = (const float*)d_in[2];
    const float* delta_log = (const float*)d_in[3];
    const float* r_log     = (const float*)d_in[4];
    float* out = (float*)d_out;

    const int F  = in_sizes[2];
    const int BF = in_sizes[0] / TT;

    const int total_warps = BF * NPAIR;
    const int threads = 128;
    const int warps_per_block = threads / 32;
    const int blocks = (total_warps + warps_per_block - 1) / warps_per_block;

    pcen_kernel<<<blocks, threads>>>(x, s_log, alpha_log, delta_log, r_log,
                                     out, F, BF);
}

// round 13
// speedup vs baseline: 1.4766x; 1.1405x over previous
#include <cuda_runtime.h>
#include <cuda_bf16.h>
#include <cstdint>

// PCEN, 10 smoother coefficients.
//   m[s,t] = (1-s)*m[s,t-1] + s*x[t],  m[s,0] = x[0]
//   out = (x*(EPS+m)^(-alpha) + delta)^r - delta^r
//
// R13: R8 structure (RPT=8, CPW=2, warp Kogge-Stone scan, fold epilogue)
// with the elementwise epilogue packed into f32x2 ops (Blackwell FFMA2 via
// PTX fma/mul/add.rn.f32x2): ~12 packed insts per 2 elements replace ~24
// scalar fma-pipe insts. MUFU (3/elem) stays scalar = the 53K-cycle floor.
// Degree-4 exp poly. Scan/IIR identical to R8/R9.

#define PCEN_EPS 1e-5f
#define NS 10
#define CPW 2
#define NPAIR (NS / CPW)
#define TT 2048
#define RPT 8
#define CHUNK (32 * RPT)          // 256
#define NCHUNK (TT / CHUNK)       // 8

typedef unsigned long long u64;

__device__ __forceinline__ float fast_ex2(float v) {
    float r; asm("ex2.approx.ftz.f32 %0, %1;" : "=f"(r) : "f"(v)); return r;
}
__device__ __forceinline__ float fast_lg2(float v) {
    float r; asm("lg2.approx.ftz.f32 %0, %1;" : "=f"(r) : "f"(v)); return r;
}

// ---- f32x2 packed helpers ----
__device__ __forceinline__ u64 pk2(float lo, float hi) {
    u64 d;
    asm("mov.b64 %0, {%1, %2};" : "=l"(d)
        : "r"(__float_as_uint(lo)), "r"(__float_as_uint(hi)));
    return d;
}
__device__ __forceinline__ void upk2(u64 v, float& lo, float& hi) {
    uint32_t a, b;
    asm("mov.b64 {%0, %1}, %2;" : "=r"(a), "=r"(b) : "l"(v));
    lo = __uint_as_float(a); hi = __uint_as_float(b);
}
__device__ __forceinline__ u64 fma2(u64 a, u64 b, u64 c) {
    u64 d; asm("fma.rn.f32x2 %0, %1, %2, %3;" : "=l"(d) : "l"(a), "l"(b), "l"(c)); return d;
}
__device__ __forceinline__ u64 mul2(u64 a, u64 b) {
    u64 d; asm("mul.rn.f32x2 %0, %1, %2;" : "=l"(d) : "l"(a), "l"(b)); return d;
}
__device__ __forceinline__ u64 add2(u64 a, u64 b) {
    u64 d; asm("add.rn.f32x2 %0, %1, %2;" : "=l"(d) : "l"(a), "l"(b)); return d;
}

// packed-constant bit patterns
#define EPS2_C   0x3727C5AC3727C5ACULL   // 1e-5f
#define MAGIC2_C 0x4B4000004B400000ULL   // 12582912.0f = 1.5*2^23
#define LN2_2_C  0x3F3172183F317218ULL   // ln(2)
#define NEG1_2_C 0xBF800000BF800000ULL   // -1.0f
#define C4_2_C   0x3D2AAAAB3D2AAAABULL   // 1/24
#define C3_2_C   0x3E2AAAAB3E2AAAABULL   // 1/6
#define HALF2_C  0x3F0000003F000000ULL   // 0.5f
#define ONE2_C   0x3F8000003F800000ULL   // 1.0f

// Packed epilogue for an element pair (u,v):
//   m = ap*Mg + l; em = m+EPS; sm = em^-alpha; base = x*sm+delta;
//   out = 2^(r*lg2(base)) - delta_r   (deg-4 exp poly, packed)
__device__ __forceinline__ void pcen_pair(
    u64 x2, u64 l2, u64 ap2, u64 Mg2,
    u64 nalpha2, u64 r2, u64 delta2, float delta_r,
    float& ou, float& ov)
{
    u64 m2  = fma2(ap2, Mg2, l2);
    u64 em2 = add2(m2, EPS2_C);
    float emu, emv; upk2(em2, emu, emv);
    u64 t2  = mul2(pk2(fast_lg2(emu), fast_lg2(emv)), nalpha2);
    float tu, tv; upk2(t2, tu, tv);
    u64 base2 = fma2(x2, pk2(fast_ex2(tu), fast_ex2(tv)), delta2);
    float bu, bv; upk2(base2, bu, bv);
    u64 v2  = mul2(pk2(fast_lg2(bu), fast_lg2(bv)), r2);
    // packed exp2: magic round + deg-4 poly + scalar exponent insert
    u64 fl2 = add2(v2, MAGIC2_C);
    u64 td2 = add2(v2, fma2(fl2, NEG1_2_C, MAGIC2_C));   // v - (fl - magic)
    u64 u2  = mul2(td2, LN2_2_C);
    u64 p2  = fma2(u2, C4_2_C, C3_2_C);
    p2 = fma2(p2, u2, HALF2_C);
    p2 = fma2(p2, u2, ONE2_C);
    p2 = fma2(p2, u2, ONE2_C);
    uint32_t flu, flv;
    asm("mov.b64 {%0, %1}, %2;" : "=r"(flu), "=r"(flv) : "l"(fl2));
    float pu, pv; upk2(p2, pu, pv);
    ou = __int_as_float(__float_as_int(pu) + ((int)flu << 23)) - delta_r;
    ov = __int_as_float(__float_as_int(pv) + ((int)flv << 23)) - delta_r;
}

__global__ __launch_bounds__(128) void pcen_kernel(
    const float* __restrict__ x,
    const float* __restrict__ s_log,
    const float* __restrict__ alpha_log,
    const float* __restrict__ delta_log,
    const float* __restrict__ r_log,
    float* __restrict__ out,
    int F, int BF)
{
    const int gwarp = (blockIdx.x * blockDim.x + threadIdx.x) >> 5;
    const int lane  = threadIdx.x & 31;
    if (gwarp >= BF * NPAIR) return;

    const int row  = gwarp / NPAIR;
    const int pair = gwarp % NPAIR;
    const int i0   = pair * CPW;

    const int b = row / F;
    const int f = row % F;

    const float alpha = __expf(alpha_log[f]);
    const float delta = __expf(delta_log[f]);
    const float r     = __expf(r_log[f]);
    const float delta_r = fast_ex2(r * fast_lg2(delta));

    const u64 nalpha2 = pk2(-alpha, -alpha);
    const u64 r2      = pk2(r, r);
    const u64 delta2  = pk2(delta, delta);

    const float4* __restrict__ xp4 = (const float4*)(x + (size_t)row * TT);
    float* __restrict__ op = out + (((size_t)b * NS + i0) * F + f) * (size_t)TT;
    const size_t s_stride = (size_t)F * TT;

    // persistent per-chain state: 7 regs per chain (R9 trim)
    float sv[CPW], a1[CPW], a2[CPW], a4[CPW], a8[CPW];
    float a8lane[CPW], carry[CPW];

    const float x0 = ((const float*)xp4)[0];

    #pragma unroll
    for (int c = 0; c < CPW; c++) {
        const float s = __expf(s_log[i0 + c]);
        sv[c] = s;
        const float a = 1.0f - s;
        a1[c] = a;
        a2[c] = a * a;
        a4[c] = a2[c] * a2[c];
        a8[c] = a4[c] * a4[c];
        const float a16  = a8[c] * a8[c];
        const float a32  = a16 * a16;
        const float a64  = a32 * a32;
        const float a128 = a64 * a64;
        float ap = 1.0f;                        // (a^8)^lane
        if (lane & 1)  ap *= a8[c];
        if (lane & 2)  ap *= a16;
        if (lane & 4)  ap *= a32;
        if (lane & 8)  ap *= a64;
        if (lane & 16) ap *= a128;
        a8lane[c] = ap;
        carry[c] = x0;   // m_{-1} = x0 -> m_0 = x0 (reference init)
    }

    for (int ch = 0; ch < NCHUNK; ch++) {
        // lane owns t in [ch*256 + lane*8, +8): two float4 loads
        const int base4 = ch * 64 + lane * 2;
        const float4 xa = xp4[base4];
        const float4 xb = xp4[base4 + 1];

        // packed x pairs, shared by both chains
        const u64 x01 = pk2(xa.x, xa.y);
        const u64 x23 = pk2(xa.z, xa.w);
        const u64 x45 = pk2(xb.x, xb.y);
        const u64 x67 = pk2(xb.z, xb.w);

        #pragma unroll
        for (int c = 0; c < CPW; c++) {
            const float s = sv[c];
            const float a = a1[c];
            // local serial IIR (zero init), 8 steps (R8-identical)
            const float l0 = s * xa.x;
            const float l1 = fmaf(a, l0, s * xa.y);
            const float l2 = fmaf(a, l1, s * xa.z);
            const float l3 = fmaf(a, l2, s * xa.w);
            const float l4 = fmaf(a, l3, s * xb.x);
            const float l5 = fmaf(a, l4, s * xb.y);
            const float l6 = fmaf(a, l5, s * xb.z);
            const float l7 = fmaf(a, l6, s * xb.w);

            // recompute scan powers (cheap)
            const float a16  = a8[c] * a8[c];
            const float a32  = a16 * a16;
            const float a64  = a32 * a32;
            const float a128 = a64 * a64;

            // Kogge-Stone over lane aggregates (ratio a^8)
            float S = l7;
            float v;
            v = __shfl_up_sync(0xFFFFFFFFu, S, 1);  if (lane >= 1)  S = fmaf(a8[c], v, S);
            v = __shfl_up_sync(0xFFFFFFFFu, S, 2);  if (lane >= 2)  S = fmaf(a16,   v, S);
            v = __shfl_up_sync(0xFFFFFFFFu, S, 4);  if (lane >= 4)  S = fmaf(a32,   v, S);
            v = __shfl_up_sync(0xFFFFFFFFu, S, 8);  if (lane >= 8)  S = fmaf(a64,   v, S);
            v = __shfl_up_sync(0xFFFFFFFFu, S, 16); if (lane >= 16) S = fmaf(a128,  v, S);

            const float P = __shfl_up_sync(0xFFFFFFFFu, S, 1);
            const float Mg = (lane == 0) ? carry[c]
                                         : fmaf(a8lane[c], carry[c], P);
            const float S31 = __shfl_sync(0xFFFFFFFFu, S, 31);
            carry[c] = fmaf(a128 * a128, carry[c], S31);

            const u64 Mg2 = pk2(Mg, Mg);
            const float a3 = a1[c] * a2[c];
            const float a5 = a1[c] * a4[c];
            const float a6 = a2[c] * a4[c];
            const float a7 = a3 * a4[c];

            float* o = op + (size_t)c * s_stride + (size_t)ch * CHUNK + lane * RPT;

            // first half: elements 0..3 (two packed pairs), store
            {
                float4 oa;
                pcen_pair(x01, pk2(l0, l1), pk2(a1[c], a2[c]), Mg2,
                          nalpha2, r2, delta2, delta_r, oa.x, oa.y);
                pcen_pair(x23, pk2(l2, l3), pk2(a3, a4[c]), Mg2,
                          nalpha2, r2, delta2, delta_r, oa.z, oa.w);
                *(float4*)o = oa;
            }
            // second half: elements 4..7, store
            {
                float4 ob;
                pcen_pair(x45, pk2(l4, l5), pk2(a5, a6), Mg2,
                          nalpha2, r2, delta2, delta_r, ob.x, ob.y);
                pcen_pair(x67, pk2(l6, l7), pk2(a7, a8[c]), Mg2,
                          nalpha2, r2, delta2, delta_r, ob.z, ob.w);
                *(float4*)(o + 4) = ob;
            }
        }
    }
}

extern "C" void kernel_launch(void* const* d_in, const int* in_sizes, int n_in,
                              void* d_out, int out_size)
{
    const float* x         = (const float*)d_in[0];
    const float* s_log     = (const float*)d_in[1];
    const float* alpha_log = (const float*)d_in[2];
    const float* delta_log = (const float*)d_in[3];
    const float* r_log     = (const float*)d_in[4];
    float* out = (float*)d_out;

    const int F  = in_sizes[2];
    const int BF = in_sizes[0] / TT;

    const int total_warps = BF * NPAIR;
    const int threads = 128;
    const int warps_per_block = threads / 32;
    const int blocks = (total_warps + warps_per_block - 1) / warps_per_block;

    pcen_kernel<<<blocks, threads>>>(x, s_log, alpha_log, delta_log, r_log,
                                     out, F, BF);
}